// round 8
// baseline (speedup 1.0000x reference)
#include <cuda_runtime.h>

// Conv2d: x[16][32][256][256] (NCHW) * w[32][32][3][3] (OIHW) + bias[32]
// fp32, stride 1, pad 1. Direct conv, packed dual-FMA (fma.rn.f32x2).
//
// R8: dual smem input copies (base + 1-float-shifted) so ALL kw taps are
// aligned LDS.64 -> zero packing movs in inner loop. 8 ci per pass (4 passes),
// 66.8KB smem/CTA -> 2 CTAs/SM. Staging offsets precomputed once (no divs).

#define TH 16
#define TW 32
#define IN_ROWS 18
#define IN_COLS 34
#define IN_STRIDE 42          // even + conflict-free: (5hh+4wg+j) mod 16 injective
#define C_IN 32
#define C_OUT 32
#define QC 8                  // channels staged per pass
#define S_IN_CH (IN_ROWS * IN_STRIDE)      // 756 floats per channel per copy
#define S_IN1_OFF (QC * S_IN_CH)           // 6048
#define S_W_OFF   (2 * QC * S_IN_CH)       // 12096 (48384B, 16B aligned)
#define SMEM_FLOATS (S_W_OFF + QC * 9 * 2 * C_OUT)   // 12096+4608=16704
#define SMEM_BYTES (SMEM_FLOATS * 4)                  // 66816 B

__device__ __forceinline__ unsigned long long pk2(float a, float b) {
    unsigned long long r;
    asm("mov.b64 %0, {%1, %2};" : "=l"(r) : "f"(a), "f"(b));
    return r;
}
__device__ __forceinline__ void upk2(unsigned long long v, float &a, float &b) {
    asm("mov.b64 {%0, %1}, %2;" : "=f"(a), "=f"(b) : "l"(v));
}
__device__ __forceinline__ void fma2(unsigned long long &d, unsigned long long a,
                                     unsigned long long b) {
    asm("fma.rn.f32x2 %0, %1, %2, %0;" : "+l"(d) : "l"(a), "l"(b));
}

__global__ __launch_bounds__(256, 2)
void conv3x3_f32x2_kernel(const float* __restrict__ x,
                          const float* __restrict__ wt,
                          const float* __restrict__ bias,
                          float* __restrict__ out)
{
    extern __shared__ float smem[];
    float* s0 = smem;                 // base copy: [ci'][18][42]
    float* s1 = smem + S_IN1_OFF;     // shifted:   s1[r][c'] = in[r][c'+1]
    float* sw = smem + S_W_OFF;       // weights dup: [(ci'*9+k)*64 + 2co]

    const int tid = threadIdx.x;
    const int n   = blockIdx.z;
    const int H0  = blockIdx.y * TH;
    const int W0  = blockIdx.x * TW;

    const int cg      = tid >> 6;
    const int co_base = cg * 8;
    const int rem     = tid & 63;
    const int hh      = rem >> 2;
    const int wbase   = (rem & 3) * 8;

    unsigned long long acc[8][4];
    #pragma unroll
    for (int i = 0; i < 8; i++) {
        float bv = __ldg(bias + co_base + i);
        unsigned long long bp = pk2(bv, bv);
        #pragma unroll
        for (int p = 0; p < 4; p++) acc[i][p] = bp;
    }

    // ---- staging precompute (once; pass-invariant): 612 positions, <=3/thread
    int  gofs[3], sofs[3];
    bool inb[3], has_s1[3];
    #pragma unroll
    for (int s = 0; s < 3; s++) {
        int pos = tid + 256 * s;
        bool active = pos < IN_ROWS * IN_COLS;       // 612
        int r = pos / IN_COLS;
        int c = pos - r * IN_COLS;
        int gh = H0 - 1 + r;
        int gw = W0 - 1 + c;
        inb[s]    = active && ((unsigned)gh < 256u) && ((unsigned)gw < 256u);
        has_s1[s] = active && (c >= 1);
        gofs[s]   = gh * 256 + gw;
        sofs[s]   = active ? (r * IN_STRIDE + c) : 0;
        if (!active) { inb[s] = false; has_s1[s] = false; }
    }
    const bool act2 = (tid + 512) < IN_ROWS * IN_COLS;

    const float* xin = x + (size_t)n * C_IN * 65536;
    const float* p0base = s0 + hh * IN_STRIDE + wbase;
    const float* p1base = s1 + hh * IN_STRIDE + wbase;

    #pragma unroll 1
    for (int q = 0; q < 4; q++) {
        // ---- weights: dup {w,w}; gmem wt[co][ci][kh][kw]
        for (int i = tid; i < C_OUT * QC * 9; i += 256) {
            int co   = i / (QC * 9);
            int rem2 = i - co * (QC * 9);
            float v  = __ldg(wt + co * (C_IN * 9) + q * (QC * 9) + rem2);
            int o = rem2 * 64 + 2 * co;
            sw[o]     = v;
            sw[o + 1] = v;
        }
        // ---- inputs: both copies, no divisions
        #pragma unroll 1
        for (int ci = 0; ci < QC; ci++) {
            const float* src = xin + (q * QC + ci) * 65536;
            float* d0 = s0 + ci * S_IN_CH;
            float* d1 = s1 + ci * S_IN_CH;
            #pragma unroll
            for (int s = 0; s < 3; s++) {
                if (s == 2 && !act2) break;
                float v = inb[s] ? __ldg(src + gofs[s]) : 0.0f;
                if (s < 2 || act2) d0[sofs[s]] = v;
                if (has_s1[s])     d1[sofs[s] - 1] = v;
            }
        }
        __syncthreads();

        #pragma unroll 1
        for (int ci = 0; ci < QC; ci++) {
            #pragma unroll
            for (int kh = 0; kh < 3; kh++) {
                const float* r0 = p0base + ci * S_IN_CH + kh * IN_STRIDE;
                const float* r1 = p1base + ci * S_IN_CH + kh * IN_STRIDE;
                unsigned long long pr0[5], pr1[4];
                #pragma unroll
                for (int j = 0; j < 5; j++)
                    pr0[j] = *(const unsigned long long*)(r0 + 2 * j);
                #pragma unroll
                for (int j = 0; j < 4; j++)
                    pr1[j] = *(const unsigned long long*)(r1 + 2 * j);

                #pragma unroll
                for (int kw = 0; kw < 3; kw++) {
                    unsigned long long wv[8];
                    const ulonglong2* wp =
                        (const ulonglong2*)sw + ((ci * 3 + kh) * 3 + kw) * 16 + cg * 4;
                    #pragma unroll
                    for (int qq = 0; qq < 4; qq++) {
                        ulonglong2 t = wp[qq];
                        wv[2 * qq]     = t.x;
                        wv[2 * qq + 1] = t.y;
                    }
                    #pragma unroll
                    for (int co = 0; co < 8; co++) {
                        #pragma unroll
                        for (int p = 0; p < 4; p++)
                            fma2(acc[co][p],
                                 wv[co],
                                 (kw == 0) ? pr0[p] : (kw == 1) ? pr1[p] : pr0[p + 1]);
                    }
                }
            }
        }
        __syncthreads();
    }

    // ---- store: 2x float4 per cout, coalesced
    float* obase = out + (((size_t)n * C_OUT + co_base) * 256 + (H0 + hh)) * 256
                       + W0 + wbase;
    #pragma unroll
    for (int co = 0; co < 8; co++) {
        float4 v0, v1;
        upk2(acc[co][0], v0.x, v0.y);
        upk2(acc[co][1], v0.z, v0.w);
        upk2(acc[co][2], v1.x, v1.y);
        upk2(acc[co][3], v1.z, v1.w);
        float* op = obase + (size_t)co * 65536;
        *(float4*)(op)     = v0;
        *(float4*)(op + 4) = v1;
    }
}

extern "C" void kernel_launch(void* const* d_in, const int* in_sizes, int n_in,
                              void* d_out, int out_size)
{
    const float* x    = (const float*)d_in[0];
    const float* wt   = (const float*)d_in[1];
    const float* bias = (const float*)d_in[2];
    float* out        = (float*)d_out;

    cudaFuncSetAttribute(conv3x3_f32x2_kernel,
                         cudaFuncAttributeMaxDynamicSharedMemorySize, SMEM_BYTES);

    dim3 grid(256 / TW, 256 / TH, 16);
    conv3x3_f32x2_kernel<<<grid, 256, SMEM_BYTES>>>(x, wt, bias, out);
}